// round 9
// baseline (speedup 1.0000x reference)
#include <cuda_runtime.h>
#include <cstdint>

// Problem constants
#define B_  128
#define C1_ 128
#define C2_ 14
#define S_  14
#define H_  256

#define THREADS 224   // 7 warps

// A (x window) smem geometry, in 8-byte PAIRS:
//   pair-addr = PM*mp + PN*n + (4*step + t);  PM=280, PN=20
//   -> LDS.64 bank pattern 4q+t (conflict-free), rows 16B-aligned
#define PM 280
#define PN 20
#define XBUF_W (16 * PM * 2)          // 8960 words per buffer
#define BS_W   (2 * XBUF_W)           // 17920
#define BS_BUF 2048                   // words per B chunk (N=64)
#define CS_STRIDE 68
#define SMEM_WORDS (BS_W + 3 * BS_BUF)   // 24064 words = 96256 B

// GEMM-ready gmem scratch (rebuilt by prep kernels every launch)
__device__ float g_xpre[(size_t)B_ * 16 * 14 * 4 * 32];   // 14.7 MB
__device__ float g_wpre[12 * 4 * 2048];                   // 393 KB

__device__ __forceinline__ float tf32r(float v) {
    float r;
    asm("cvt.rna.tf32.f32 %0, %1;" : "=f"(r) : "f"(v));
    return r;
}

__device__ __forceinline__ void mma_tf32(float c[4],
                                         unsigned a0, unsigned a1, unsigned a2, unsigned a3,
                                         unsigned b0, unsigned b1) {
    asm volatile(
        "mma.sync.aligned.m16n8k8.row.col.f32.tf32.tf32.f32 "
        "{%0,%1,%2,%3}, {%4,%5,%6,%7}, {%8,%9}, {%0,%1,%2,%3};"
        : "+f"(c[0]), "+f"(c[1]), "+f"(c[2]), "+f"(c[3])
        : "r"(a0), "r"(a1), "r"(a2), "r"(a3), "r"(b0), "r"(b1));
}

__device__ __forceinline__ void cp16(unsigned dst, const void* src) {
    asm volatile("cp.async.cg.shared.global [%0], [%1], 16;"
                 :: "r"(dst), "l"(src) : "memory");
}
#define CP_COMMIT() asm volatile("cp.async.commit_group;" ::: "memory")
#define CP_WAIT1()  asm volatile("cp.async.wait_group 1;" ::: "memory")

// ---------------------------------------------------------------------------
// prep_x: pure gather permutation. Block = one (b, mp, nn) 128-word row;
// thread tid -> (jb = tid>>5, pp = tid&31). Coalesced 512B row stores.
//   j = 8*step + t + 4*h  where pp = 2*(4*step+t)+h
//   value = tf32(x[b, (jb*32+j)*14 + nn, mp-1]),  0 for pad planes mp=0,15
// ---------------------------------------------------------------------------
__global__ __launch_bounds__(128) void prep_x(const float* __restrict__ x) {
    const int bx  = blockIdx.x;           // 0 .. 128*16*14-1
    const int b   = bx / 224;
    const int r   = bx - b * 224;
    const int mp  = r / 14;
    const int nn  = r - (r / 14) * 14;
    const int tid = threadIdx.x;

    float v = 0.0f;
    if (mp >= 1 && mp <= 14) {
        const int jb = tid >> 5, pp = tid & 31;
        const int p = pp >> 1, h = pp & 1;
        const int jj = 8 * (p >> 2) + (p & 3) + 4 * h;
        v = tf32r(__ldg(x + (size_t)b * 25088 + ((jb * 32 + jj) * 14 + nn) * 14 + (mp - 1)));
    }
    g_xpre[((size_t)(b * 16 + mp) * 14 + nn) * 128 + tid] = v;
}

// ---------------------------------------------------------------------------
// prep_w: wpre[c:12][hh:4][step:4][n:64][t:4][h2:2], tf32-rounded.
// value = w1[j = (c/3)*32 + 8*step + t + 4*h2,  i = c%3,  hcol = hh*64+n]
// ---------------------------------------------------------------------------
__global__ __launch_bounds__(256) void prep_w(const float* __restrict__ w1) {
    int idx = blockIdx.x * 256 + threadIdx.x;
    if (idx >= 12 * 4 * 2048) return;
    int h2   = idx & 1;
    int t    = (idx >> 1) & 3;
    int n    = (idx >> 3) & 63;
    int step = (idx >> 9) & 3;
    int hh   = (idx >> 11) & 3;
    int c    = idx >> 13;
    int j    = (c / 3) * 32 + 8 * step + t + 4 * h2;
    int i    = c - (c / 3) * 3;
    g_wpre[idx] = tf32r(w1[(size_t)(j * 3 + i) * H_ + hh * 64 + n]);
}

// ---------------------------------------------------------------------------
// Fused GEMM + roll epilogue. Block = (b, 64-h chunk). M=224 rows r=(m*14+n),
// N=64, K=384=(i,j), tf32 MMA, cp.async pipelined (3-deep B, 2-deep x).
// ---------------------------------------------------------------------------
__global__ void __launch_bounds__(THREADS, 2) fused_kernel(
    const float* __restrict__ w0,      // (H, 2)
    const int*   __restrict__ shift_p, // scalar (may be null -> 1)
    float*       __restrict__ out)     // (B, H, C2, S)
{
    extern __shared__ float sm[];
    const unsigned sbase = (unsigned)__cvta_generic_to_shared(sm);

    const int bid = blockIdx.x;
    const int b   = bid >> 2;
    const int hh  = bid & 3;
    const int h0  = hh * 64;

    const int tid  = threadIdx.x;
    const int w    = tid >> 5;
    const int lane = tid & 31;
    const int t    = lane & 3;
    const int q    = lane >> 2;

    // x staging: one 32-float row per thread per jb
    const int smp = tid / 14;
    const int snn = tid - smp * 14;
    const float* xsrc0 = g_xpre + (((size_t)b * 16 + smp) * 14 + snn) * 128;
    const unsigned xdst0 = sbase + (unsigned)((PM * smp + PN * snn) * 2) * 4u;

    auto issue_x = [&](int jb) {
        const float* src = xsrc0 + jb * 32;
        unsigned dst = xdst0 + (unsigned)((jb & 1) * XBUF_W) * 4u;
#pragma unroll
        for (int k = 0; k < 8; ++k) cp16(dst + 16u * k, src + 4 * k);
    };
    // B staging: 2048 floats = 512 x 16B
    auto issue_b = [&](int c2, int buf) {
        const float* src = g_wpre + ((size_t)c2 * 4 + hh) * 2048;
        unsigned dst = sbase + (unsigned)(BS_W + buf * BS_BUF) * 4u;
#pragma unroll
        for (int k = 0; k < 3; ++k) {
            int p = tid + k * THREADS;
            if (p < 512) cp16(dst + 16u * p, src + 4 * p);
        }
    };

    // Per-thread A base offsets (words)
    int pa[4];
#pragma unroll
    for (int u = 0; u < 4; ++u) {
        int r  = 32 * w + q + 8 * u;
        int mr = r / 14;
        int nr = r - mr * 14;
        if (mr > 13) mr = 13;          // pad rows -> harmless valid data
        pa[u] = 2 * (PM * mr + PN * nr + t);
    }

    // Prologue: chunk0 (x0+B0), chunk1 (B1)
    issue_x(0);
    issue_b(0, 0);
    CP_COMMIT();
    issue_b(1, 1);
    CP_COMMIT();

    float cf[16][4];
#pragma unroll
    for (int f = 0; f < 16; ++f)
#pragma unroll
        for (int r = 0; r < 4; ++r) cf[f][r] = 0.0f;

    const int pbq = q * 8 + 2 * t;

    // ---- Main loop: 12 chunks = 4 j-blocks x 3 i (chunk c=3jb+ii, buf=c%3=ii) ----
#pragma unroll 1
    for (int jb = 0; jb < 4; ++jb) {
        const int xw = (jb & 1) * XBUF_W;

#pragma unroll
        for (int ii = 0; ii < 3; ++ii) {
            CP_WAIT1();
            __syncthreads();

            if (3 * jb + ii < 10) {
                if (ii == 1) issue_x(jb + 1);
                issue_b(3 * jb + ii + 2, (ii + 2) % 3);
                CP_COMMIT();
            }

            const int bw = BS_W + ii * BS_BUF + pbq;
            const int aw = xw + 560 * ii;            // 2*PM*ii

#pragma unroll
            for (int step = 0; step < 4; ++step) {
                const int ao = aw + 8 * step;
                float2 aA = *reinterpret_cast<const float2*>(&sm[pa[0] + ao]);
                float2 aB = *reinterpret_cast<const float2*>(&sm[pa[1] + ao]);
                float2 aC = *reinterpret_cast<const float2*>(&sm[pa[2] + ao]);
                float2 aD = *reinterpret_cast<const float2*>(&sm[pa[3] + ao]);
#pragma unroll
                for (int fn = 0; fn < 8; ++fn) {
                    float2 bp = *reinterpret_cast<const float2*>(
                        &sm[bw + step * 512 + fn * 64]);
                    unsigned b0 = __float_as_uint(bp.x);
                    unsigned b1 = __float_as_uint(bp.y);
                    mma_tf32(cf[fn],
                             __float_as_uint(aA.x), __float_as_uint(aB.x),
                             __float_as_uint(aA.y), __float_as_uint(aB.y), b0, b1);
                    mma_tf32(cf[8 + fn],
                             __float_as_uint(aC.x), __float_as_uint(aD.x),
                             __float_as_uint(aC.y), __float_as_uint(aD.y), b0, b1);
                }
            }
        }
    }

    __syncthreads();   // C tile (15232 w) overlaps x buffer 1 -> must drain reads

    // ---- Write C tile to smem rows [r][CS_STRIDE] ----
#pragma unroll
    for (int fm = 0; fm < 2; ++fm) {
#pragma unroll
        for (int fn = 0; fn < 8; ++fn) {
            const float* cc = cf[fm * 8 + fn];
            int r1  = 32 * w + 16 * fm + q;
            int r2  = r1 + 8;
            int col = 8 * fn + 2 * t;
            *reinterpret_cast<float2*>(&sm[r1 * CS_STRIDE + col]) = make_float2(cc[0], cc[1]);
            *reinterpret_cast<float2*>(&sm[r2 * CS_STRIDE + col]) = make_float2(cc[2], cc[3]);
        }
    }
    __syncthreads();

    // ---- Fused roll epilogue: 64 h x 14 n rows, 4 iters ----
    const int s   = shift_p ? shift_p[0] : 1;
    const int s28 = ((s % 28) + 28) % 28;
    const int s14 = ((s % 14) + 14) % 14;

#pragma unroll
    for (int it = 0; it < 4; ++it) {
        int idx = it * THREADS + tid;   // 0..895
        int h_l = idx & 63;
        int nb  = idx >> 6;             // 0..13

        float2 w0p = __ldg(reinterpret_cast<const float2*>(w0) + (h0 + h_l));

        int n2[2];
        float wv[2];
#pragma unroll
        for (int e = 0; e < 2; ++e) {
            int g  = (nb * 2 + e - s28 + 56) % 28;
            int n1 = g >> 1;
            int e1 = g & 1;
            n2[e]  = (n1 - s14 + 14) % 14;
            wv[e]  = e1 ? w0p.y : w0p.x;
        }

        float* orow = out + (size_t)(b * H_ + h0 + h_l) * (C2_ * S_) + nb * S_;
#pragma unroll
        for (int mm = 0; mm < 7; ++mm) {
            int m0 = 2 * mm, m1 = 2 * mm + 1;
            float v0 = sm[(m0 * 14 + n2[0]) * CS_STRIDE + h_l] * wv[0]
                     + sm[(m0 * 14 + n2[1]) * CS_STRIDE + h_l] * wv[1];
            float v1 = sm[(m1 * 14 + n2[0]) * CS_STRIDE + h_l] * wv[0]
                     + sm[(m1 * 14 + n2[1]) * CS_STRIDE + h_l] * wv[1];
            *reinterpret_cast<float2*>(orow + m0) = make_float2(v0, v1);
        }
    }
}

// ---------------------------------------------------------------------------
extern "C" void kernel_launch(void* const* d_in, const int* in_sizes, int n_in,
                              void* d_out, int out_size)
{
    const float* x     = (const float*)d_in[0];
    const float* w0    = (const float*)d_in[1];
    const float* w1    = (const float*)d_in[2];
    const int*   shift = (n_in >= 4) ? (const int*)d_in[3] : nullptr;

    (void)in_sizes; (void)out_size;

    prep_x<<<B_ * 16 * 14, 128>>>(x);
    prep_w<<<(12 * 4 * 2048 + 255) / 256, 256>>>(w1);

    cudaFuncSetAttribute(fused_kernel,
                         cudaFuncAttributeMaxDynamicSharedMemorySize,
                         SMEM_WORDS * 4);
    fused_kernel<<<B_ * 4, THREADS, SMEM_WORDS * 4>>>(w0, shift, (float*)d_out);
}

// round 10
// speedup vs baseline: 1.1215x; 1.1215x over previous
#include <cuda_runtime.h>
#include <cstdint>

// Problem constants
#define B_  128
#define C1_ 128
#define C2_ 14
#define S_  14
#define H_  256

#define THREADS 224   // 7 warps

// A (x window) smem geometry, in 8-byte PAIRS:
//   pair-addr = PM*mp + PN*n + (4*step + t);  PM=280, PN=20
//   -> LDS.64 bank pattern 4q+t (conflict-free), rows 16B-aligned
#define PM 280
#define PN 20
#define XBUF_W (16 * PM * 2)          // 8960 words per buffer
#define BS_W   (2 * XBUF_W)           // 17920
#define BS_BUF 2048                   // words per B chunk (N=64)
#define NBUF_B 4                      // B pipeline depth
#define CS_STRIDE 68
#define SMEM_WORDS (BS_W + NBUF_B * BS_BUF)   // 26112 words = 104448 B

// GEMM-ready gmem scratch (rebuilt by prep kernels every launch)
__device__ float g_xpre[(size_t)B_ * 16 * 14 * 4 * 32];   // 14.7 MB
__device__ float g_wpre[12 * 4 * 2048];                   // 393 KB

__device__ __forceinline__ float tf32r(float v) {
    float r;
    asm("cvt.rna.tf32.f32 %0, %1;" : "=f"(r) : "f"(v));
    return r;
}

__device__ __forceinline__ void mma_tf32(float c[4],
                                         unsigned a0, unsigned a1, unsigned a2, unsigned a3,
                                         unsigned b0, unsigned b1) {
    asm volatile(
        "mma.sync.aligned.m16n8k8.row.col.f32.tf32.tf32.f32 "
        "{%0,%1,%2,%3}, {%4,%5,%6,%7}, {%8,%9}, {%0,%1,%2,%3};"
        : "+f"(c[0]), "+f"(c[1]), "+f"(c[2]), "+f"(c[3])
        : "r"(a0), "r"(a1), "r"(a2), "r"(a3), "r"(b0), "r"(b1));
}

__device__ __forceinline__ void cp16(unsigned dst, const void* src) {
    asm volatile("cp.async.cg.shared.global [%0], [%1], 16;"
                 :: "r"(dst), "l"(src) : "memory");
}
#define CP_COMMIT() asm volatile("cp.async.commit_group;" ::: "memory")
#define CP_WAIT2()  asm volatile("cp.async.wait_group 2;" ::: "memory")

// ---------------------------------------------------------------------------
// prep_x: block (jb, b), 448 threads. Coalesced read of the 6272-float
// (b, 32-j) slice into smem, then divide-free permuted write:
//   tid -> (nn = tid>>5, pp = tid&31); loop mp 0..15 (planes 0,15 -> zero pad)
//   j = 8*(p>>2) + (p&3) + 4*h  where pp = 2p + h
// Warp stores are 128B-contiguous (fixed nn, pp 0..31).
// ---------------------------------------------------------------------------
__global__ __launch_bounds__(448) void prep_x(const float* __restrict__ x) {
    __shared__ float xs[6272];
    const int jb = blockIdx.x;
    const int b  = blockIdx.y;
    const int tid = threadIdx.x;

    const float4* src = reinterpret_cast<const float4*>(x + (size_t)b * 25088 + jb * 6272);
#pragma unroll
    for (int k = 0; k < 4; ++k) {
        int p = tid + k * 448;
        if (p < 1568) reinterpret_cast<float4*>(xs)[p] = __ldg(src + p);
    }
    __syncthreads();

    const int nn = tid >> 5;
    const int pp = tid & 31;
    const int p  = pp >> 1, h = pp & 1;
    const int j  = 8 * (p >> 2) + (p & 3) + 4 * h;
    const float* rbase = xs + j * 196 + nn * 14;

    float* wbase = g_xpre + ((size_t)b * 16 * 14 + nn) * 128 + jb * 32 + pp;
#pragma unroll
    for (int mp = 0; mp < 16; ++mp) {
        float v = (mp >= 1 && mp <= 14) ? tf32r(rbase[mp - 1]) : 0.0f;
        wbase[(size_t)mp * 14 * 128] = v;
    }
}

// ---------------------------------------------------------------------------
// prep_w: wpre[c:12][hh:4][step:4][n:64][t:4][h2:2], tf32-rounded.
// value = w1[j = (c/3)*32 + 8*step + t + 4*h2,  i = c%3,  hcol = hh*64+n]
// ---------------------------------------------------------------------------
__global__ __launch_bounds__(256) void prep_w(const float* __restrict__ w1) {
    int idx = blockIdx.x * 256 + threadIdx.x;
    if (idx >= 12 * 4 * 2048) return;
    int h2   = idx & 1;
    int t    = (idx >> 1) & 3;
    int n    = (idx >> 3) & 63;
    int step = (idx >> 9) & 3;
    int hh   = (idx >> 11) & 3;
    int c    = idx >> 13;
    int j    = (c / 3) * 32 + 8 * step + t + 4 * h2;
    int i    = c - (c / 3) * 3;
    g_wpre[idx] = tf32r(w1[(size_t)(j * 3 + i) * H_ + hh * 64 + n]);
}

// ---------------------------------------------------------------------------
// Fused GEMM + roll epilogue. Block = (b, 64-h chunk). M=224 rows r=(m*14+n),
// N=64, K=384=(i,j), tf32 MMA. cp.async: B 4-deep / x 2-deep, prefetch
// distance 3 chunks, wait_group 2 -> staging latency fully off-path.
// ---------------------------------------------------------------------------
__global__ void __launch_bounds__(THREADS, 2) fused_kernel(
    const float* __restrict__ w0,      // (H, 2)
    const int*   __restrict__ shift_p, // scalar (may be null -> 1)
    float*       __restrict__ out)     // (B, H, C2, S)
{
    extern __shared__ float sm[];
    const unsigned sbase = (unsigned)__cvta_generic_to_shared(sm);

    const int bid = blockIdx.x;
    const int b   = bid >> 2;
    const int hh  = bid & 3;
    const int h0  = hh * 64;

    const int tid  = threadIdx.x;
    const int w    = tid >> 5;
    const int lane = tid & 31;
    const int t    = lane & 3;
    const int q    = lane >> 2;

    // x staging: one 32-float row per thread per jb
    const int smp = tid / 14;
    const int snn = tid - smp * 14;
    const float* xsrc0 = g_xpre + (((size_t)b * 16 + smp) * 14 + snn) * 128;
    const unsigned xdst0 = sbase + (unsigned)((PM * smp + PN * snn) * 2) * 4u;

    auto issue_x = [&](int jb) {
        const float* src = xsrc0 + jb * 32;
        unsigned dst = xdst0 + (unsigned)((jb & 1) * XBUF_W) * 4u;
#pragma unroll
        for (int k = 0; k < 8; ++k) cp16(dst + 16u * k, src + 4 * k);
    };
    // B staging: 2048 floats = 512 x 16B
    auto issue_b = [&](int c2, int buf) {
        const float* src = g_wpre + ((size_t)c2 * 4 + hh) * 2048;
        unsigned dst = sbase + (unsigned)(BS_W + buf * BS_BUF) * 4u;
#pragma unroll
        for (int k = 0; k < 3; ++k) {
            int p = tid + k * THREADS;
            if (p < 512) cp16(dst + 16u * p, src + 4 * p);
        }
    };

    // Per-thread A base offsets (words)
    int pa[4];
#pragma unroll
    for (int u = 0; u < 4; ++u) {
        int r  = 32 * w + q + 8 * u;
        int mr = r / 14;
        int nr = r - mr * 14;
        if (mr > 13) mr = 13;          // pad rows -> harmless valid data
        pa[u] = 2 * (PM * mr + PN * nr + t);
    }

    // Prologue: x0 + B chunks 0,1,2 (three commit groups)
    issue_x(0);
    issue_b(0, 0);
    CP_COMMIT();
    issue_b(1, 1);
    CP_COMMIT();
    issue_b(2, 2);
    CP_COMMIT();

    float cf[16][4];
#pragma unroll
    for (int f = 0; f < 16; ++f)
#pragma unroll
        for (int r = 0; r < 4; ++r) cf[f][r] = 0.0f;

    const int pbq = q * 8 + 2 * t;

    // ---- Main loop: 12 chunks = 4 j-blocks x 3 i.
    // Group math: chunk c lives in commit-group c+1; at the top of chunk c the
    // newest group is c+3, so wait_group(2) guarantees chunk c is resident. ----
#pragma unroll 1
    for (int jb = 0; jb < 4; ++jb) {
        const int xw = (jb & 1) * XBUF_W;

#pragma unroll
        for (int ii = 0; ii < 3; ++ii) {
            CP_WAIT2();
            __syncthreads();

            const int c = 3 * jb + ii;
            if (ii == 0 && jb < 3) issue_x(jb + 1);   // x(jb+1) in group c+4,
                                                      // needed at chunk 3jb+3 ✓
            if (c < 9) issue_b(c + 3, (c + 3) & 3);
            CP_COMMIT();

            const int bw = BS_W + (c & 3) * BS_BUF + pbq;
            const int aw = xw + 560 * ii;             // 2*PM*ii

#pragma unroll
            for (int step = 0; step < 4; ++step) {
                const int ao = aw + 8 * step;
                float2 aA = *reinterpret_cast<const float2*>(&sm[pa[0] + ao]);
                float2 aB = *reinterpret_cast<const float2*>(&sm[pa[1] + ao]);
                float2 aC = *reinterpret_cast<const float2*>(&sm[pa[2] + ao]);
                float2 aD = *reinterpret_cast<const float2*>(&sm[pa[3] + ao]);
#pragma unroll
                for (int fn = 0; fn < 8; ++fn) {
                    float2 bp = *reinterpret_cast<const float2*>(
                        &sm[bw + step * 512 + fn * 64]);
                    unsigned b0 = __float_as_uint(bp.x);
                    unsigned b1 = __float_as_uint(bp.y);
                    mma_tf32(cf[fn],
                             __float_as_uint(aA.x), __float_as_uint(aB.x),
                             __float_as_uint(aA.y), __float_as_uint(aB.y), b0, b1);
                    mma_tf32(cf[8 + fn],
                             __float_as_uint(aC.x), __float_as_uint(aD.x),
                             __float_as_uint(aC.y), __float_as_uint(aD.y), b0, b1);
                }
            }
        }
    }

    __syncthreads();   // C tile overlaps x buffers -> drain all reads first

    // ---- Write C tile to smem rows [r][CS_STRIDE] ----
#pragma unroll
    for (int fm = 0; fm < 2; ++fm) {
#pragma unroll
        for (int fn = 0; fn < 8; ++fn) {
            const float* cc = cf[fm * 8 + fn];
            int r1  = 32 * w + 16 * fm + q;
            int r2  = r1 + 8;
            int col = 8 * fn + 2 * t;
            *reinterpret_cast<float2*>(&sm[r1 * CS_STRIDE + col]) = make_float2(cc[0], cc[1]);
            *reinterpret_cast<float2*>(&sm[r2 * CS_STRIDE + col]) = make_float2(cc[2], cc[3]);
        }
    }
    __syncthreads();

    // ---- Fused roll epilogue: 64 h x 14 n rows, 4 iters ----
    const int s   = shift_p ? shift_p[0] : 1;
    const int s28 = ((s % 28) + 28) % 28;
    const int s14 = ((s % 14) + 14) % 14;

#pragma unroll
    for (int it = 0; it < 4; ++it) {
        int idx = it * THREADS + tid;   // 0..895
        int h_l = idx & 63;
        int nb  = idx >> 6;             // 0..13

        float2 w0p = __ldg(reinterpret_cast<const float2*>(w0) + (h0 + h_l));

        int n2[2];
        float wv[2];
#pragma unroll
        for (int e = 0; e < 2; ++e) {
            int g  = (nb * 2 + e - s28 + 56) % 28;
            int n1 = g >> 1;
            int e1 = g & 1;
            n2[e]  = (n1 - s14 + 14) % 14;
            wv[e]  = e1 ? w0p.y : w0p.x;
        }

        float* orow = out + (size_t)(b * H_ + h0 + h_l) * (C2_ * S_) + nb * S_;
#pragma unroll
        for (int mm = 0; mm < 7; ++mm) {
            int m0 = 2 * mm, m1 = 2 * mm + 1;
            float v0 = sm[(m0 * 14 + n2[0]) * CS_STRIDE + h_l] * wv[0]
                     + sm[(m0 * 14 + n2[1]) * CS_STRIDE + h_l] * wv[1];
            float v1 = sm[(m1 * 14 + n2[0]) * CS_STRIDE + h_l] * wv[0]
                     + sm[(m1 * 14 + n2[1]) * CS_STRIDE + h_l] * wv[1];
            *reinterpret_cast<float2*>(orow + m0) = make_float2(v0, v1);
        }
    }
}

// ---------------------------------------------------------------------------
extern "C" void kernel_launch(void* const* d_in, const int* in_sizes, int n_in,
                              void* d_out, int out_size)
{
    const float* x     = (const float*)d_in[0];
    const float* w0    = (const float*)d_in[1];
    const float* w1    = (const float*)d_in[2];
    const int*   shift = (n_in >= 4) ? (const int*)d_in[3] : nullptr;

    (void)in_sizes; (void)out_size;

    dim3 gx(4, B_);
    prep_x<<<gx, 448>>>(x);
    prep_w<<<(12 * 4 * 2048 + 255) / 256, 256>>>(w1);

    cudaFuncSetAttribute(fused_kernel,
                         cudaFuncAttributeMaxDynamicSharedMemorySize,
                         SMEM_WORDS * 4);
    fused_kernel<<<B_ * 4, THREADS, SMEM_WORDS * 4>>>(w0, shift, (float*)d_out);
}

// round 11
// speedup vs baseline: 1.1707x; 1.0439x over previous
#include <cuda_runtime.h>
#include <cstdint>

// Problem constants
#define B_  128
#define C1_ 128
#define C2_ 14
#define S_  14
#define H_  256

#define THREADS 224   // 7 warps

// A (x window) smem geometry, in 8-byte PAIRS:
//   pair-addr = 280*lp + 20*n + (4*step + t)   (lp = local mp plane, 0..8)
//   word bank of LDS.64 = (20r + t) mod 16 = (4q + t) -> conflict-free
#define XBUF_W (9 * 560)              // 5040 words per buffer (9 planes)
#define BS_W   (2 * XBUF_W)           // 10080
#define BS_BUF 2048                   // words per B chunk (N=64)
#define NBUF_B 4
#define CS_STRIDE 68
#define SMEM_WORDS (BS_W + NBUF_B * BS_BUF)   // 18272 words = 73088 B -> 3 CTA/SM

// GEMM-ready gmem scratch (rebuilt by prep kernels every launch)
__device__ float g_xpre[(size_t)B_ * 16 * 14 * 4 * 32];   // 14.7 MB
__device__ float g_wpre[12 * 4 * 2048];                   // 393 KB

__device__ __forceinline__ float tf32r(float v) {
    float r;
    asm("cvt.rna.tf32.f32 %0, %1;" : "=f"(r) : "f"(v));
    return r;
}

__device__ __forceinline__ void mma_tf32(float c[4],
                                         unsigned a0, unsigned a1, unsigned a2, unsigned a3,
                                         unsigned b0, unsigned b1) {
    asm volatile(
        "mma.sync.aligned.m16n8k8.row.col.f32.tf32.tf32.f32 "
        "{%0,%1,%2,%3}, {%4,%5,%6,%7}, {%8,%9}, {%0,%1,%2,%3};"
        : "+f"(c[0]), "+f"(c[1]), "+f"(c[2]), "+f"(c[3])
        : "r"(a0), "r"(a1), "r"(a2), "r"(a3), "r"(b0), "r"(b1));
}

__device__ __forceinline__ void cp16(unsigned dst, const void* src) {
    asm volatile("cp.async.cg.shared.global [%0], [%1], 16;"
                 :: "r"(dst), "l"(src) : "memory");
}
#define CP_COMMIT() asm volatile("cp.async.commit_group;" ::: "memory")
#define CP_WAIT2()  asm volatile("cp.async.wait_group 2;" ::: "memory")

// ---------------------------------------------------------------------------
// prep_x: block (jb, b), 448 threads. Coalesced slice read -> smem -> permuted
// 128B-coalesced writes. xpre[b][mp:16][n:14][jb:4][pp:32], zero pad planes.
// ---------------------------------------------------------------------------
__global__ __launch_bounds__(448) void prep_x(const float* __restrict__ x) {
    __shared__ float xs[6272];
    const int jb = blockIdx.x;
    const int b  = blockIdx.y;
    const int tid = threadIdx.x;

    const float4* src = reinterpret_cast<const float4*>(x + (size_t)b * 25088 + jb * 6272);
#pragma unroll
    for (int k = 0; k < 4; ++k) {
        int p = tid + k * 448;
        if (p < 1568) reinterpret_cast<float4*>(xs)[p] = __ldg(src + p);
    }
    __syncthreads();

    const int nn = tid >> 5;
    const int pp = tid & 31;
    const int p  = pp >> 1, h = pp & 1;
    const int j  = 8 * (p >> 2) + (p & 3) + 4 * h;
    const float* rbase = xs + j * 196 + nn * 14;

    float* wbase = g_xpre + ((size_t)b * 16 * 14 + nn) * 128 + jb * 32 + pp;
#pragma unroll
    for (int mp = 0; mp < 16; ++mp) {
        float v = (mp >= 1 && mp <= 14) ? tf32r(rbase[mp - 1]) : 0.0f;
        wbase[(size_t)mp * 14 * 128] = v;
    }
}

// ---------------------------------------------------------------------------
// prep_w: wpre[c:12][hh:4][step:4][n:64][t:4][h2:2], tf32-rounded.
// ---------------------------------------------------------------------------
__global__ __launch_bounds__(256) void prep_w(const float* __restrict__ w1) {
    int idx = blockIdx.x * 256 + threadIdx.x;
    if (idx >= 12 * 4 * 2048) return;
    int h2   = idx & 1;
    int t    = (idx >> 1) & 3;
    int n    = (idx >> 3) & 63;
    int step = (idx >> 9) & 3;
    int hh   = (idx >> 11) & 3;
    int c    = idx >> 13;
    int j    = (c / 3) * 32 + 8 * step + t + 4 * h2;
    int i    = c - (c / 3) * 3;
    g_wpre[idx] = tf32r(w1[(size_t)(j * 3 + i) * H_ + hh * 64 + n]);
}

// ---------------------------------------------------------------------------
// Fused GEMM + roll epilogue. Block = (b, m-half, 64-h chunk).
// M=112 rows r=(m_loc*14+n) with m_loc 0..6 (m = 7*mh + m_loc), N=64, K=384.
// Only 9 x planes needed per block -> 73 KB smem -> 3 CTAs/SM.
// Warp tile m16 x n64. cp.async: B 4-deep, x 2-deep, distance 3, wait 2.
// ---------------------------------------------------------------------------
__global__ void __launch_bounds__(THREADS, 3) fused_kernel(
    const float* __restrict__ w0,      // (H, 2)
    const int*   __restrict__ shift_p, // scalar (may be null -> 1)
    float*       __restrict__ out)     // (B, H, C2, S)
{
    extern __shared__ float sm[];
    const unsigned sbase = (unsigned)__cvta_generic_to_shared(sm);

    const int bid = blockIdx.x;
    const int b   = bid >> 3;
    const int mh  = (bid >> 2) & 1;
    const int hh  = bid & 3;
    const int h0  = hh * 64;

    const int tid  = threadIdx.x;
    const int w    = tid >> 5;
    const int lane = tid & 31;
    const int t    = lane & 3;
    const int q    = lane >> 2;

    // ---- x staging: 9 planes x 14 n x 32 = 1008 x 16B, 5 cp16/thread ----
    int xlp[5], xnn[5], xqd[5];
#pragma unroll
    for (int k = 0; k < 5; ++k) {
        int p = tid + k * THREADS;
        if (p < 1008) {
            int row = p >> 3;
            xqd[k] = p & 7;
            xlp[k] = row / 14;
            xnn[k] = row - xlp[k] * 14;
        } else xlp[k] = -1;
    }
    const float* xpb = g_xpre + ((size_t)b * 16 + 7 * mh) * 14 * 128;

    auto issue_x = [&](int jb) {
        unsigned dbase = sbase + (unsigned)((jb & 1) * XBUF_W) * 4u;
#pragma unroll
        for (int k = 0; k < 5; ++k) {
            if (xlp[k] >= 0) {
                const float* src = xpb + (size_t)(xlp[k] * 14 + xnn[k]) * 128
                                 + jb * 32 + xqd[k] * 4;
                unsigned dst = dbase + (unsigned)(560 * xlp[k] + 40 * xnn[k]
                                                  + 4 * xqd[k]) * 4u;
                cp16(dst, src);
            }
        }
    };
    // ---- B staging: 2048 floats = 512 x 16B ----
    auto issue_b = [&](int c2, int buf) {
        const float* src = g_wpre + ((size_t)c2 * 4 + hh) * 2048;
        unsigned dst = sbase + (unsigned)(BS_W + buf * BS_BUF) * 4u;
#pragma unroll
        for (int k = 0; k < 3; ++k) {
            int p = tid + k * THREADS;
            if (p < 512) cp16(dst + 16u * p, src + 4 * p);
        }
    };

    // Per-thread A base offsets (words): rows q and q+8 of warp tile m16
    int pa[2];
#pragma unroll
    for (int u = 0; u < 2; ++u) {
        int r  = 16 * w + q + 8 * u;
        int mr = r / 14;
        int nr = r - mr * 14;
        if (mr > 6) mr = 6;            // pad rows -> harmless valid data
        pa[u] = 2 * (280 * mr + 20 * nr + t);
    }

    // Prologue: x0 + B chunks 0,1,2
    issue_x(0);
    issue_b(0, 0);
    CP_COMMIT();
    issue_b(1, 1);
    CP_COMMIT();
    issue_b(2, 2);
    CP_COMMIT();

    float cf[8][4];
#pragma unroll
    for (int f = 0; f < 8; ++f)
#pragma unroll
        for (int r = 0; r < 4; ++r) cf[f][r] = 0.0f;

    const int pbq = q * 8 + 2 * t;

    // ---- Main loop: 12 chunks = 4 j-blocks x 3 i.
    // chunk c in group c+1; newest group at top of c is c+3; wait(2) -> c+1 done ----
#pragma unroll 1
    for (int jb = 0; jb < 4; ++jb) {
        const int xw = (jb & 1) * XBUF_W;

#pragma unroll
        for (int ii = 0; ii < 3; ++ii) {
            CP_WAIT2();
            __syncthreads();

            const int c = 3 * jb + ii;
            if (ii == 0 && jb < 3) issue_x(jb + 1);
            if (c < 9) issue_b(c + 3, (c + 3) & 3);
            CP_COMMIT();

            const int bw = BS_W + (c & 3) * BS_BUF + pbq;
            const int aw = xw + 560 * ii;

#pragma unroll
            for (int step = 0; step < 4; ++step) {
                const int ao = aw + 8 * step;
                float2 aA = *reinterpret_cast<const float2*>(&sm[pa[0] + ao]);
                float2 aB = *reinterpret_cast<const float2*>(&sm[pa[1] + ao]);
                unsigned a0 = __float_as_uint(aA.x), a1 = __float_as_uint(aB.x);
                unsigned a2 = __float_as_uint(aA.y), a3 = __float_as_uint(aB.y);
#pragma unroll
                for (int fn = 0; fn < 8; ++fn) {
                    float2 bp = *reinterpret_cast<const float2*>(
                        &sm[bw + step * 512 + fn * 64]);
                    mma_tf32(cf[fn], a0, a1, a2, a3,
                             __float_as_uint(bp.x), __float_as_uint(bp.y));
                }
            }
        }
    }

    __syncthreads();   // C tile aliases x region -> drain reads

    // ---- Write C tile to smem rows [r][CS_STRIDE] (112 x 68 = 7616 w) ----
#pragma unroll
    for (int fn = 0; fn < 8; ++fn) {
        const float* cc = cf[fn];
        int r1  = 16 * w + q;
        int r2  = r1 + 8;
        int col = 8 * fn + 2 * t;
        *reinterpret_cast<float2*>(&sm[r1 * CS_STRIDE + col]) = make_float2(cc[0], cc[1]);
        *reinterpret_cast<float2*>(&sm[r2 * CS_STRIDE + col]) = make_float2(cc[2], cc[3]);
    }
    __syncthreads();

    // ---- Fused roll epilogue: 64 h x 14 n, 7 m each ----
    const int s   = shift_p ? shift_p[0] : 1;
    const int s28 = ((s % 28) + 28) % 28;
    const int s14 = ((s % 14) + 14) % 14;

#pragma unroll
    for (int it = 0; it < 4; ++it) {
        int idx = it * THREADS + tid;   // 0..895
        int h_l = idx & 63;
        int nb  = idx >> 6;             // 0..13

        float2 w0p = __ldg(reinterpret_cast<const float2*>(w0) + (h0 + h_l));

        int n2[2];
        float wv[2];
#pragma unroll
        for (int e = 0; e < 2; ++e) {
            int g  = (nb * 2 + e - s28 + 56) % 28;
            int n1 = g >> 1;
            int e1 = g & 1;
            n2[e]  = (n1 - s14 + 14) % 14;
            wv[e]  = e1 ? w0p.y : w0p.x;
        }

        float* obase = out + ((size_t)(b * H_ + h0 + h_l) * C2_ + nb) * S_ + 7 * mh;
#pragma unroll
        for (int mm = 0; mm < 7; ++mm) {
            float v = sm[(mm * 14 + n2[0]) * CS_STRIDE + h_l] * wv[0]
                    + sm[(mm * 14 + n2[1]) * CS_STRIDE + h_l] * wv[1];
            obase[mm] = v;
        }
    }
}

// ---------------------------------------------------------------------------
extern "C" void kernel_launch(void* const* d_in, const int* in_sizes, int n_in,
                              void* d_out, int out_size)
{
    const float* x     = (const float*)d_in[0];
    const float* w0    = (const float*)d_in[1];
    const float* w1    = (const float*)d_in[2];
    const int*   shift = (n_in >= 4) ? (const int*)d_in[3] : nullptr;

    (void)in_sizes; (void)out_size;

    dim3 gx(4, B_);
    prep_x<<<gx, 448>>>(x);
    prep_w<<<(12 * 4 * 2048 + 255) / 256, 256>>>(w1);

    cudaFuncSetAttribute(fused_kernel,
                         cudaFuncAttributeMaxDynamicSharedMemorySize,
                         SMEM_WORDS * 4);
    fused_kernel<<<B_ * 8, THREADS, SMEM_WORDS * 4>>>(w0, shift, (float*)d_out);
}

// round 13
// speedup vs baseline: 1.4610x; 1.2479x over previous
#include <cuda_runtime.h>
#include <cuda_fp16.h>
#include <cstdint>

// Problem constants
#define B_  128
#define C2_ 14
#define S_  14
#define H_  256

#define THREADS 224   // 7 warps

// A (x window) smem geometry, word units (1 word = 4B = 1 half2 slot):
//   addr = 336*plane + 24*n + slot ;  336 = 14*24 so 336*mr+24*nr = 24*r
//   row stride 24 (== 24 mod 32) -> LDS.64 banks 24q+2t conflict-free
#define ROW_S   24
#define PLANE_S 336
#define XBUF_W  (9 * PLANE_S)        // 3024 words per buffer (9 planes)
#define BS_W    (2 * XBUF_W)         // 6048
#define BS_BUF  (64 * ROW_S)         // 1536 words per B chunk (N=64)
#define NBUF_B  4
#define CS_STRIDE 68
#define SMEM_WORDS (BS_W + NBUF_B * BS_BUF)   // 12192 words = 48768 B

// Packed fp16 k-pair scratch (rebuilt each launch)
//  g_xpre[b][mp:16][n:14][jb:4][slot:16] : half2 = (j=2p, j=2p+1) of block jb
//  g_wpre[c:12][hq:4][n:64][slot:16]     : half2 = w1 pairs for chunk c
__device__ __half2 g_xpre[(size_t)B_ * 16 * 14 * 64];   // 7.3 MB
__device__ __half2 g_wpre[12 * 4 * 64 * 16];            // 196 KB

// slot s -> pair p  (inverse of addr(p) = (p&8)|((p&3)<<1)|((p&4)>>2))
__device__ __forceinline__ int slot2pair(int s) {
    return (s & 8) | ((s >> 1) & 3) | ((s & 1) << 2);
}

__device__ __forceinline__ void mma_f16(float c[4],
                                        unsigned a0, unsigned a1, unsigned a2, unsigned a3,
                                        unsigned b0, unsigned b1) {
    asm volatile(
        "mma.sync.aligned.m16n8k16.row.col.f32.f16.f16.f32 "
        "{%0,%1,%2,%3}, {%4,%5,%6,%7}, {%8,%9}, {%0,%1,%2,%3};"
        : "+f"(c[0]), "+f"(c[1]), "+f"(c[2]), "+f"(c[3])
        : "r"(a0), "r"(a1), "r"(a2), "r"(a3), "r"(b0), "r"(b1));
}

__device__ __forceinline__ void cp16(unsigned dst, const void* src) {
    asm volatile("cp.async.cg.shared.global [%0], [%1], 16;"
                 :: "r"(dst), "l"(src) : "memory");
}
#define CP_COMMIT() asm volatile("cp.async.commit_group;" ::: "memory")
#define CP_WAIT2()  asm volatile("cp.async.wait_group 2;" ::: "memory")

// ---------------------------------------------------------------------------
// prep_x: block (jb, b), 448 threads. Coalesced slice read -> smem; write
// half2 k-pairs in interleaved slot order. Planes mp=0,15 are zero pad.
// ---------------------------------------------------------------------------
__global__ __launch_bounds__(448) void prep_x(const float* __restrict__ x) {
    __shared__ float xs[6272];
    const int jb = blockIdx.x;
    const int b  = blockIdx.y;
    const int tid = threadIdx.x;

    const float4* src = reinterpret_cast<const float4*>(x + (size_t)b * 25088 + jb * 6272);
#pragma unroll
    for (int k = 0; k < 4; ++k) {
        int p = tid + k * 448;
        if (p < 1568) reinterpret_cast<float4*>(xs)[p] = __ldg(src + p);
    }
    __syncthreads();

    const int half = tid >= 224;
    const int sub  = tid - 224 * half;
    const int nn   = sub >> 4;          // 0..13
    const int s    = sub & 15;
    const int pp   = slot2pair(s);
    const float* r0 = xs + (2 * pp)     * 196 + nn * 14;
    const float* r1 = xs + (2 * pp + 1) * 196 + nn * 14;

    __half2* wb = g_xpre + ((size_t)b * 16 * 14 + nn) * 64 + jb * 16 + s;
#pragma unroll
    for (int k = 0; k < 8; ++k) {
        int mp = 8 * half + k;
        __half2 v = (mp >= 1 && mp <= 14)
                  ? __floats2half2_rn(r0[mp - 1], r1[mp - 1])
                  : __floats2half2_rn(0.0f, 0.0f);
        wb[(size_t)mp * 14 * 64] = v;
    }
}

// ---------------------------------------------------------------------------
// prep_w: half2 pairs (j=2p, 2p+1) of w1[j, i, h] for chunk c = 3*jb + ii.
// ---------------------------------------------------------------------------
__global__ __launch_bounds__(256) void prep_w(const float* __restrict__ w1) {
    int idx = blockIdx.x * 256 + threadIdx.x;
    if (idx >= 12 * 4 * 64 * 16) return;
    int s  = idx & 15;
    int n  = (idx >> 4) & 63;
    int hq = (idx >> 10) & 3;
    int c  = idx >> 12;
    int jb = c / 3;
    int ii = c - 3 * jb;
    int pp = slot2pair(s);
    int j  = jb * 32 + 2 * pp;
    int h  = hq * 64 + n;
    float lo = __ldg(w1 + (size_t)(j * 3 + ii) * H_ + h);
    float hi = __ldg(w1 + (size_t)((j + 1) * 3 + ii) * H_ + h);
    g_wpre[idx] = __floats2half2_rn(lo, hi);
}

// ---------------------------------------------------------------------------
// Fused fp16 GEMM + roll epilogue. Block = (b, m-half, 64-h chunk).
// M=112 rows r=(m_loc*14+n), N=64, K=384 in 12 chunks of 32 (2 k16 MMAs each).
// cp.async: B 4-deep, x 2-deep, distance 3, wait_group 2.
// ---------------------------------------------------------------------------
__global__ void __launch_bounds__(THREADS, 3) fused_kernel(
    const float* __restrict__ w0,      // (H, 2)
    const int*   __restrict__ shift_p, // scalar (may be null -> 1)
    float*       __restrict__ out)     // (B, H, C2, S)
{
    extern __shared__ float sm[];
    unsigned sbase;
    asm("{ .reg .u64 t; cvta.to.shared.u64 t, %1; cvt.u32.u64 %0, t; }"
        : "=r"(sbase) : "l"(sm));

    const int bid = blockIdx.x;
    const int b   = bid >> 3;
    const int mh  = (bid >> 2) & 1;
    const int hh  = bid & 3;
    const int h0  = hh * 64;

    const int tid  = threadIdx.x;
    const int w    = tid >> 5;
    const int lane = tid & 31;
    const int t    = lane & 3;
    const int q    = lane >> 2;

    // ---- x staging indices: 126 rows x 4 segs = 504 cp16, 3/thread ----
    int xlp[3], xnn[3], xsg[3];
#pragma unroll
    for (int k = 0; k < 3; ++k) {
        int p = tid + k * THREADS;
        if (p < 504) {
            int row = p >> 2;
            xsg[k] = p & 3;
            xlp[k] = row / 14;
            xnn[k] = row - xlp[k] * 14;
        } else xlp[k] = -1;
    }
    const __half2* xpb = g_xpre + ((size_t)b * 16 + 7 * mh) * 14 * 64;

    auto issue_x = [&](int jb) {
        unsigned dbase = sbase + (unsigned)((jb & 1) * XBUF_W) * 4u;
#pragma unroll
        for (int k = 0; k < 3; ++k) {
            if (xlp[k] >= 0) {
                const __half2* src = xpb + (size_t)(xlp[k] * 14 + xnn[k]) * 64
                                   + jb * 16 + xsg[k] * 4;
                unsigned dst = dbase + (unsigned)(PLANE_S * xlp[k] + ROW_S * xnn[k]
                                                  + 4 * xsg[k]) * 4u;
                cp16(dst, src);
            }
        }
    };
    // ---- B staging: 64 rows x 4 segs = 256 cp16, 2/thread ----
    auto issue_b = [&](int c2, int buf) {
        const __half2* bsrc = g_wpre + (size_t)(c2 * 4 + hh) * 1024;
        unsigned dbase = sbase + (unsigned)(BS_W + buf * BS_BUF) * 4u;
#pragma unroll
        for (int k = 0; k < 2; ++k) {
            int p = tid + k * THREADS;
            if (p < 256) {
                int row = p >> 2, seg = p & 3;
                cp16(dbase + (unsigned)(row * ROW_S + 4 * seg) * 4u,
                     bsrc + row * 16 + seg * 4);
            }
        }
    };

    // Per-thread A base offsets (words): rows q, q+8 of warp tile m16
    int pa[2];
#pragma unroll
    for (int u = 0; u < 2; ++u) {
        int r  = 16 * w + q + 8 * u;
        int mr = r / 14;
        int nr = r - mr * 14;
        if (mr > 6) mr = 6;            // pad rows -> harmless valid data
        pa[u] = PLANE_S * mr + ROW_S * nr + 2 * t;
    }

    // Prologue: x0 + B chunks 0,1,2
    issue_x(0);
    issue_b(0, 0);
    CP_COMMIT();
    issue_b(1, 1);
    CP_COMMIT();
    issue_b(2, 2);
    CP_COMMIT();

    float cf[8][4];
#pragma unroll
    for (int f = 0; f < 8; ++f)
#pragma unroll
        for (int r = 0; r < 4; ++r) cf[f][r] = 0.0f;

    const int pbq = ROW_S * q + 2 * t;

    // ---- Main loop: 12 chunks = 4 j-blocks x 3 i; 2 k16 MMA steps each ----
#pragma unroll 1
    for (int jb = 0; jb < 4; ++jb) {
        const int xw = (jb & 1) * XBUF_W;

#pragma unroll
        for (int ii = 0; ii < 3; ++ii) {
            CP_WAIT2();
            __syncthreads();

            const int c = 3 * jb + ii;
            if (ii == 0 && jb < 3) issue_x(jb + 1);
            if (c < 9) issue_b(c + 3, (c + 3) & 3);
            CP_COMMIT();

            const int bw = BS_W + (c & 3) * BS_BUF + pbq;
            const int aw = xw + PLANE_S * ii;

#pragma unroll
            for (int s = 0; s < 2; ++s) {
                const int ao = aw + 8 * s;
                float2 L1 = *reinterpret_cast<const float2*>(&sm[pa[0] + ao]);
                float2 L2 = *reinterpret_cast<const float2*>(&sm[pa[1] + ao]);
                unsigned a0 = __float_as_uint(L1.x), a2 = __float_as_uint(L1.y);
                unsigned a1 = __float_as_uint(L2.x), a3 = __float_as_uint(L2.y);
#pragma unroll
                for (int fn = 0; fn < 8; ++fn) {
                    float2 bp = *reinterpret_cast<const float2*>(
                        &sm[bw + fn * (8 * ROW_S) + 8 * s]);
                    mma_f16(cf[fn], a0, a1, a2, a3,
                            __float_as_uint(bp.x), __float_as_uint(bp.y));
                }
            }
        }
    }

    __syncthreads();   // C tile aliases x/B regions -> drain reads first

    // ---- Write C tile to smem rows [r][CS_STRIDE] (112 x 68 = 7616 w) ----
#pragma unroll
    for (int fn = 0; fn < 8; ++fn) {
        const float* cc = cf[fn];
        int r1  = 16 * w + q;
        int r2  = r1 + 8;
        int col = 8 * fn + 2 * t;
        *reinterpret_cast<float2*>(&sm[r1 * CS_STRIDE + col]) = make_float2(cc[0], cc[1]);
        *reinterpret_cast<float2*>(&sm[r2 * CS_STRIDE + col]) = make_float2(cc[2], cc[3]);
    }
    __syncthreads();

    // ---- Fused roll epilogue: 64 h x 14 n, 7 m each ----
    const int s_  = shift_p ? shift_p[0] : 1;
    const int s28 = ((s_ % 28) + 28) % 28;
    const int s14 = ((s_ % 14) + 14) % 14;

#pragma unroll
    for (int it = 0; it < 4; ++it) {
        int idx = it * THREADS + tid;   // 0..895
        int h_l = idx & 63;
        int nb  = idx >> 6;             // 0..13

        float2 w0p = __ldg(reinterpret_cast<const float2*>(w0) + (h0 + h_l));

        int n2[2];
        float wv[2];
#pragma unroll
        for (int e = 0; e < 2; ++e) {
            int g  = (nb * 2 + e - s28 + 56) % 28;
            int n1 = g >> 1;
            int e1 = g & 1;
            n2[e]  = (n1 - s14 + 14) % 14;
            wv[e]  = e1 ? w0p.y : w0p.x;
        }

        float* obase = out + ((size_t)(b * H_ + h0 + h_l) * C2_ + nb) * S_ + 7 * mh;
#pragma unroll
        for (int mm = 0; mm < 7; ++mm) {
            float v = sm[(mm * 14 + n2[0]) * CS_STRIDE + h_l] * wv[0]
                    + sm[(mm * 14 + n2[1]) * CS_STRIDE + h_l] * wv[1];
            obase[mm] = v;
        }
    }
}

// ---------------------------------------------------------------------------
extern "C" void kernel_launch(void* const* d_in, const int* in_sizes, int n_in,
                              void* d_out, int out_size)
{
    const float* x     = (const float*)d_in[0];
    const float* w0    = (const float*)d_in[1];
    const float* w1    = (const float*)d_in[2];
    const int*   shift = (n_in >= 4) ? (const int*)d_in[3] : nullptr;

    (void)in_sizes; (void)out_size;

    dim3 gx(4, B_);
    prep_x<<<gx, 448>>>(x);
    prep_w<<<(12 * 4 * 64 * 16 + 255) / 256, 256>>>(w1);

    cudaFuncSetAttribute(fused_kernel,
                         cudaFuncAttributeMaxDynamicSharedMemorySize,
                         SMEM_WORDS * 4);
    fused_kernel<<<B_ * 8, THREADS, SMEM_WORDS * 4>>>(w0, shift, (float*)d_out);
}